// round 6
// baseline (speedup 1.0000x reference)
#include <cuda_runtime.h>
#include <math.h>

// ---- problem constants ----
#define HD   128
#define HQ   32
#define HKV  8
#define SQC  4096
#define SKVC 4096
#define BQ   128
#define BKV  128
#define WIN  512
#define CAPV 50.0f
#define EPSV 1e-5f

#define PITCH  132   // smem row pitch in floats (float4 aligned)
#define RPITCH 17    // reduction buffer pitch
#define GRID_MIN 152 // GB300 has 152 SMs
#define CHUNK4 4096  // float4 per copy chunk (64 KB traffic each way)

// work-stealing chunk counter (reset each launch via captured cudaMemsetAsync)
__device__ unsigned int g_ctr;

__device__ __forceinline__ float warp_sum(float v) {
    #pragma unroll
    for (int o = 16; o; o >>= 1) v += __shfl_xor_sync(0xffffffffu, v, o);
    return v;
}

__global__ __launch_bounds__(256, 1)
void oswa_fused(const float* __restrict__ q, const float* __restrict__ k,
                const float* __restrict__ v, const float* __restrict__ g_o,
                const float* __restrict__ g_lse, const float* __restrict__ gq,
                const float* __restrict__ gk, const int* __restrict__ p_biq,
                const int* __restrict__ p_bikv,
                float* __restrict__ out_o, float* __restrict__ out_lse,
                int natt, unsigned long long o4, unsigned long long lse4,
                unsigned nchunk_o, unsigned nchunk_tot)
{
    extern __shared__ float sm[];
    __shared__ int chunk_s;

    const int tid = threadIdx.x;

    // =====================  ATTENTION (bids < natt)  =====================
    if ((int)blockIdx.x < natt) {
        float* sQ = sm;                    // [128][132] normalized Q; later P
        float* sK = sm + BQ * PITCH;       // [128][132] normalized K (rotated); later red[]
        float* sV = sm + 2 * BQ * PITCH;   // [128][132] V (interleaved)

        __shared__ float rowmax_s[BQ];
        __shared__ float co_s[BQ];
        __shared__ float cb_s[BQ];

        const int bh  = blockIdx.x;
        const int b   = bh >> 5;
        const int h   = bh & 31;
        const int kvh = h / (HQ / HKV);
        const int biq  = __ldg(p_biq);
        const int bikv = __ldg(p_bikv);

        const int lane = tid & 31;
        const int warp = tid >> 5;
        const float scale = 0.08838834764831845f;  // 1/sqrt(128)

        // ---------- load + RMS-norm Q,K; load V (swizzled stores) ----------
        {
            const float4 gqv = ((const float4*)(gq + (size_t)h * HD))[lane];
            const float4 gkv = ((const float4*)(gk + (size_t)kvh * HD))[lane];
            const int vslot = ((lane >> 1) | ((lane & 1) << 4));
            for (int r = warp * 16; r < warp * 16 + 16; ++r) {
                float4 x = ((const float4*)(q + ((size_t)(b * BQ + r) * HQ + h) * HD))[lane];
                float ssq = warp_sum(x.x * x.x + x.y * x.y + x.z * x.z + x.w * x.w);
                float riq = rsqrtf(ssq * (1.0f / HD) + EPSV);
                float4 qv; qv.x = x.x * riq * gqv.x; qv.y = x.y * riq * gqv.y;
                           qv.z = x.z * riq * gqv.z; qv.w = x.w * riq * gqv.w;
                *(float4*)&sQ[r * PITCH + lane * 4] = qv;

                float4 y = ((const float4*)(k + ((size_t)(b * BKV + r) * HKV + kvh) * HD))[lane];
                float ssk = warp_sum(y.x * y.x + y.y * y.y + y.z * y.z + y.w * y.w);
                float rik = rsqrtf(ssk * (1.0f / HD) + EPSV);
                float4 kv2; kv2.x = y.x * rik * gkv.x; kv2.y = y.y * rik * gkv.y;
                            kv2.z = y.z * rik * gkv.z; kv2.w = y.w * rik * gkv.w;
                int kslot = (lane + (r >> 3)) & 31;
                *(float4*)&sK[r * PITCH + kslot * 4] = kv2;

                float4 z = ((const float4*)(v + ((size_t)(b * BKV + r) * HKV + kvh) * HD))[lane];
                *(float4*)&sV[r * PITCH + vslot * 4] = z;
            }
        }
        __syncthreads();

        const int tr = tid >> 4;
        const int tc = tid & 15;
        const int r0 = tr * 8;
        const int c0 = tc * 8;

        // ---------- GEMM1: S = Qn @ Kn^T (ping-pong double-buffered) ----------
        float acc[8][8];
        #pragma unroll
        for (int i = 0; i < 8; ++i)
            #pragma unroll
            for (int j = 0; j < 8; ++j) acc[i][j] = 0.0f;

        auto ldkb = [&](float4* kb, int d4) {
            const int ks = ((d4 + tc) & 31) * 4;
            #pragma unroll
            for (int j = 0; j < 8; ++j)
                kb[j] = *(const float4*)&sK[(c0 + j) * PITCH + ks];
        };
        auto g1step = [&](const float4* kb, int d4) {
            #pragma unroll
            for (int i = 0; i < 8; ++i) {
                float4 a = *(const float4*)&sQ[(r0 + i) * PITCH + d4 * 4];
                #pragma unroll
                for (int j = 0; j < 8; ++j) {
                    acc[i][j] = fmaf(a.x, kb[j].x, acc[i][j]);
                    acc[i][j] = fmaf(a.y, kb[j].y, acc[i][j]);
                    acc[i][j] = fmaf(a.z, kb[j].z, acc[i][j]);
                    acc[i][j] = fmaf(a.w, kb[j].w, acc[i][j]);
                }
            }
        };

        {
            float4 kbA[8], kbB[8];
            ldkb(kbA, 0);
            for (int d4 = 0; d4 < 32; d4 += 2) {
                ldkb(kbB, d4 + 1);
                g1step(kbA, d4);
                if (d4 + 2 < 32) ldkb(kbA, d4 + 2);
                g1step(kbB, d4 + 1);
            }
        }
        __syncthreads();   // done reading sQ/sK

        // ---------- scale + poly-tanh cap + mask + row max ----------
        float* red = sK;   // reuse as [BQ][RPITCH]
        const int qbase = biq * BQ;
        const int kbase = bikv * BKV;
        const int offs  = SKVC - SQC;
        #pragma unroll
        for (int i = 0; i < 8; ++i) {
            const int qi = qbase + r0 + i;
            float m = -INFINITY;
            #pragma unroll
            for (int j = 0; j < 8; ++j) {
                const int kj = kbase + c0 + j;
                float x = acc[i][j] * scale;
                // CAP*tanh(x/CAP): |x/CAP| << 1, Taylor to u^4 (rel err < 1e-9 here)
                float u  = x * (1.0f / CAPV);
                float u2 = u * u;
                float s  = x * (1.0f - u2 * (1.0f / 3.0f) + u2 * u2 * (2.0f / 15.0f));
                const bool allowed = (kj <= qi + offs) && (kj >= qi + offs - WIN) &&
                                     (qi < SQC) && (kj < SKVC);
                s = allowed ? s : -INFINITY;
                acc[i][j] = s;
                m = fmaxf(m, s);
            }
            red[(r0 + i) * RPITCH + tc] = m;
        }
        __syncthreads();
        if (tid < BQ) {
            float m = -INFINITY;
            #pragma unroll
            for (int t = 0; t < 16; ++t) m = fmaxf(m, red[tid * RPITCH + t]);
            rowmax_s[tid] = m;
        }
        __syncthreads();

        // ---------- exp (unnormalized), write P, partial sums ----------
        float* sP = sQ;
        #pragma unroll
        for (int i = 0; i < 8; ++i) {
            const float m = rowmax_s[r0 + i];
            float s = 0.0f;
            float pv[8];
            #pragma unroll
            for (int j = 0; j < 8; ++j) {
                pv[j] = (m == -INFINITY) ? 0.0f : __expf(acc[i][j] - m);
                s += pv[j];
            }
            float4 p0, p1;
            p0.x = pv[0]; p0.y = pv[1]; p0.z = pv[2]; p0.w = pv[3];
            p1.x = pv[4]; p1.y = pv[5]; p1.z = pv[6]; p1.w = pv[7];
            *(float4*)&sP[(r0 + i) * PITCH + c0]     = p0;
            *(float4*)&sP[(r0 + i) * PITCH + c0 + 4] = p1;
            red[(r0 + i) * RPITCH + tc] = s;
        }
        __syncthreads();

        // ---------- per-row: lse_blk, merge coefficients, lse write ----------
        if (tid < BQ) {
            float s = 0.0f;
            #pragma unroll
            for (int t = 0; t < 16; ++t) s += red[tid * RPITCH + t];
            const float m = rowmax_s[tid];
            const float lse_blk = (s > 0.0f && m > -INFINITY) ? (m + logf(s)) : -INFINITY;

            const int grow = qbase + tid;
            const float lo = g_lse[((size_t)b * HQ + h) * SQC + grow];
            const float m2 = fmaxf(lo, lse_blk);
            float lnew, co, cb;
            if (m2 == -INFINITY) {
                lnew = -INFINITY; co = 0.0f; cb = 0.0f;
            } else {
                float e0 = (lo == -INFINITY) ? 0.0f : expf(lo - m2);
                float e1 = (lse_blk == -INFINITY) ? 0.0f : expf(lse_blk - m2);
                lnew = m2 + logf(e0 + e1);
                co = (lo == -INFINITY) ? 0.0f : expf(lo - lnew);
                cb = (lse_blk == -INFINITY) ? 0.0f : expf(lse_blk - lnew);
            }
            co_s[tid] = co;
            cb_s[tid] = (s > 0.0f) ? (cb / s) : 0.0f;
            out_lse[((size_t)b * HQ + h) * SQC + grow] = lnew;
        }
        __syncthreads();

        // ---------- GEMM2: O_blk = P @ V (ping-pong double-buffered) ----------
        float acc2[8][8];
        #pragma unroll
        for (int i = 0; i < 8; ++i)
            #pragma unroll
            for (int j = 0; j < 8; ++j) acc2[i][j] = 0.0f;

        auto ldpa = [&](float4* pa, int k4) {
            #pragma unroll
            for (int i = 0; i < 8; ++i)
                pa[i] = *(const float4*)&sP[(r0 + i) * PITCH + k4 * 4];
        };
        auto g2step = [&](const float4* pa, int k4) {
            const int kk = k4 * 4;
            #pragma unroll
            for (int kl = 0; kl < 4; ++kl) {
                const float4 v0 = *(const float4*)&sV[(kk + kl) * PITCH + tc * 4];
                const float4 v1 = *(const float4*)&sV[(kk + kl) * PITCH + tc * 4 + 64];
                #pragma unroll
                for (int i = 0; i < 8; ++i) {
                    const float p = ((const float*)&pa[i])[kl];
                    acc2[i][0] = fmaf(p, v0.x, acc2[i][0]);
                    acc2[i][1] = fmaf(p, v0.y, acc2[i][1]);
                    acc2[i][2] = fmaf(p, v0.z, acc2[i][2]);
                    acc2[i][3] = fmaf(p, v0.w, acc2[i][3]);
                    acc2[i][4] = fmaf(p, v1.x, acc2[i][4]);
                    acc2[i][5] = fmaf(p, v1.y, acc2[i][5]);
                    acc2[i][6] = fmaf(p, v1.z, acc2[i][6]);
                    acc2[i][7] = fmaf(p, v1.w, acc2[i][7]);
                }
            }
        };

        {
            float4 paA[8], paB[8];
            ldpa(paA, 0);
            for (int k4 = 0; k4 < 32; k4 += 2) {
                ldpa(paB, k4 + 1);
                g2step(paA, k4);
                if (k4 + 2 < 32) ldpa(paA, k4 + 2);
                g2step(paB, k4 + 1);
            }
        }

        // ---------- merge with old global O and write ----------
        #pragma unroll
        for (int i = 0; i < 8; ++i) {
            const int r = r0 + i;
            const int grow = qbase + r;
            const size_t base = (((size_t)b * SQC + grow) * HQ + h) * HD + c0;
            const float co = co_s[r];
            const float cb = cb_s[r];
            float4 g0 = __ldcs((const float4*)&g_o[base]);
            float4 g1 = __ldcs((const float4*)&g_o[base + 4]);
            float4 o0, o1;
            o0.x = co * g0.x + cb * acc2[i][0]; o0.y = co * g0.y + cb * acc2[i][1];
            o0.z = co * g0.z + cb * acc2[i][2]; o0.w = co * g0.w + cb * acc2[i][3];
            o1.x = co * g1.x + cb * acc2[i][4]; o1.y = co * g1.y + cb * acc2[i][5];
            o1.z = co * g1.z + cb * acc2[i][6]; o1.w = co * g1.w + cb * acc2[i][7];
            __stcs((float4*)&out_o[base],     o0);
            __stcs((float4*)&out_o[base + 4], o1);
        }
    }

    // =============  WORK-STEALING COPY (all CTAs end up here)  =============
    {
        const unsigned qbase = (unsigned)(__ldg(p_biq) * BQ);
        const unsigned qb4   = qbase >> 2;
        const float4* __restrict__ so = (const float4*)g_o;
        float4* __restrict__ doo = (float4*)out_o;
        const float4* __restrict__ sl = (const float4*)g_lse;
        float4* __restrict__ dl = (float4*)out_lse;

        for (;;) {
            __syncthreads();
            if (tid == 0) chunk_s = (int)atomicAdd(&g_ctr, 1u);
            __syncthreads();
            const unsigned c = (unsigned)chunk_s;
            if (c >= nchunk_tot) break;

            if (c < nchunk_o) {
                // chunk covers exactly 4 seq rows; block membership is uniform
                // (qbase = biq*128 and CHUNK4 rows = 4 both 4-aligned)
                const unsigned r0g = (4u * c) & (SQC - 1u);
                if ((r0g - qbase) < (unsigned)BQ) continue;   // attention writes these
                const size_t base = (size_t)c * CHUNK4 + tid;
                float4 r[16]; bool ok[16];
                #pragma unroll
                for (int u = 0; u < 16; ++u) {
                    const size_t ii = base + (size_t)u * 256;
                    ok[u] = (ii < (size_t)o4);
                    if (ok[u]) r[u] = __ldcs(so + ii);
                }
                #pragma unroll
                for (int u = 0; u < 16; ++u)
                    if (ok[u]) __stcs(doo + base + (size_t)u * 256, r[u]);
            } else {
                const size_t base = (size_t)(c - nchunk_o) * CHUNK4 + tid;
                #pragma unroll
                for (int u = 0; u < 16; ++u) {
                    const size_t ii = base + (size_t)u * 256;
                    if (ii >= (size_t)lse4) continue;
                    const unsigned col = (unsigned)ii & 1023u;  // 1024 f4 per (b,h) row
                    if ((col - qb4) < 32u) continue;            // attention writes these
                    __stcs(dl + ii, __ldcs(sl + ii));
                }
            }
        }
    }
}

extern "C" void kernel_launch(void* const* d_in, const int* in_sizes, int n_in,
                              void* d_out, int out_size)
{
    const float* q     = (const float*)d_in[0];
    const float* k     = (const float*)d_in[1];
    const float* v     = (const float*)d_in[2];
    const float* g_o   = (const float*)d_in[3];
    const float* g_lse = (const float*)d_in[4];
    const float* gq    = (const float*)d_in[5];
    const float* gk    = (const float*)d_in[6];
    const int*   biq   = (const int*)d_in[7];
    const int*   bikv  = (const int*)d_in[8];

    float* out = (float*)d_out;

    const int b_dim = in_sizes[0] / (BQ * HQ * HD);                 // 4
    const unsigned long long o_elems   = (unsigned long long)in_sizes[3];
    const unsigned long long lse_elems = (unsigned long long)in_sizes[4];
    const int natt = b_dim * HQ;                                    // 128

    const unsigned long long o4   = o_elems >> 2;
    const unsigned long long lse4 = lse_elems >> 2;
    const unsigned nchunk_o   = (unsigned)((o4 + CHUNK4 - 1) / CHUNK4);
    const unsigned nchunk_tot = nchunk_o + (unsigned)((lse4 + CHUNK4 - 1) / CHUNK4);

    // reset the work-stealing counter (captured as a memset node)
    void* ctr_ptr = nullptr;
    cudaGetSymbolAddress(&ctr_ptr, g_ctr);
    cudaMemsetAsync(ctr_ptr, 0, sizeof(unsigned), 0);

    const size_t smem = (size_t)3 * BQ * PITCH * sizeof(float);     // 202752 B
    cudaFuncSetAttribute(oswa_fused,
                         cudaFuncAttributeMaxDynamicSharedMemorySize, (int)smem);

    // attention CTAs first (long pole), plus pure-copy CTAs to fill all SMs
    const int fill = (natt < GRID_MIN) ? (GRID_MIN - natt) : 8;
    oswa_fused<<<natt + fill, 256, smem, 0>>>(
        q, k, v, g_o, g_lse, gq, gk, biq, bikv,
        out, out + o_elems, natt, o4, lse4, nchunk_o, nchunk_tot);
}

// round 8
// speedup vs baseline: 1.3863x; 1.3863x over previous
#include <cuda_runtime.h>
#include <cuda_fp16.h>
#include <math.h>
#include <stdint.h>

// ---- problem constants ----
#define HD   128
#define HQ   32
#define HKV  8
#define SQC  4096
#define SKVC 4096
#define BQ   128
#define BKV  128
#define WIN  512
#define CAPV 50.0f
#define EPSV 1e-5f

#define PH     136   // smem half pitch (272B rows: 16B-aligned, ldmatrix conflict-free)
#define NCOPY  1024  // copy CTAs (static grid-stride, R3-proven)

__device__ __forceinline__ float warp_sum(float v) {
    #pragma unroll
    for (int o = 16; o; o >>= 1) v += __shfl_xor_sync(0xffffffffu, v, o);
    return v;
}

__device__ __forceinline__ void ldsm4(uint32_t& r0, uint32_t& r1, uint32_t& r2, uint32_t& r3,
                                      uint32_t addr) {
    asm volatile("ldmatrix.sync.aligned.m8n8.x4.shared.b16 {%0,%1,%2,%3}, [%4];"
                 : "=r"(r0), "=r"(r1), "=r"(r2), "=r"(r3) : "r"(addr));
}
__device__ __forceinline__ void ldsm2(uint32_t& r0, uint32_t& r1, uint32_t addr) {
    asm volatile("ldmatrix.sync.aligned.m8n8.x2.shared.b16 {%0,%1}, [%2];"
                 : "=r"(r0), "=r"(r1) : "r"(addr));
}
__device__ __forceinline__ void ldsm2t(uint32_t& r0, uint32_t& r1, uint32_t addr) {
    asm volatile("ldmatrix.sync.aligned.m8n8.x2.trans.shared.b16 {%0,%1}, [%2];"
                 : "=r"(r0), "=r"(r1) : "r"(addr));
}
__device__ __forceinline__ void mma16816(float* c, const uint32_t* a, uint32_t b0, uint32_t b1) {
    asm volatile(
        "mma.sync.aligned.m16n8k16.row.col.f32.f16.f16.f32 "
        "{%0,%1,%2,%3}, {%4,%5,%6,%7}, {%8,%9}, {%0,%1,%2,%3};"
        : "+f"(c[0]), "+f"(c[1]), "+f"(c[2]), "+f"(c[3])
        : "r"(a[0]), "r"(a[1]), "r"(a[2]), "r"(a[3]), "r"(b0), "r"(b1));
}
__device__ __forceinline__ uint32_t packh2(float lo, float hi) {
    __half2 h = __floats2half2_rn(lo, hi);
    return *reinterpret_cast<uint32_t*>(&h);
}

__global__ __launch_bounds__(256, 1)
void oswa_fused(const float* __restrict__ q, const float* __restrict__ k,
                const float* __restrict__ v, const float* __restrict__ g_o,
                const float* __restrict__ g_lse, const float* __restrict__ gq,
                const float* __restrict__ gk, const int* __restrict__ p_biq,
                const int* __restrict__ p_bikv,
                float* __restrict__ out_o, float* __restrict__ out_lse,
                int natt, unsigned long long o4, unsigned long long lse4)
{
    const int tid = threadIdx.x;

    // =====================  COPY BRANCH (bids >= natt)  =====================
    if ((int)blockIdx.x >= natt) {
        const int cid = blockIdx.x - natt;
        const unsigned qbase = (unsigned)(__ldg(p_biq) * BQ);

        const float4* __restrict__ src = (const float4*)g_o;
        float4* __restrict__ dst = (float4*)out_o;
        const size_t n4 = (size_t)o4;
        const size_t stride = (size_t)NCOPY * 1024;
        for (size_t i = (size_t)cid * 1024 + tid; i < n4; i += stride) {
            float4 r[4]; bool ok[4];
            #pragma unroll
            for (int u = 0; u < 4; ++u) {
                size_t ii = i + (size_t)u * 256;
                ok[u] = (ii < n4);
                if (ok[u]) {
                    unsigned row = (unsigned)(ii >> 10);      // 1024 float4 per seq row
                    unsigned s   = row & (SQC - 1);
                    if ((s - qbase) < (unsigned)BQ) ok[u] = false;
                    else r[u] = src[ii];
                }
            }
            #pragma unroll
            for (int u = 0; u < 4; ++u)
                if (ok[u]) dst[i + (size_t)u * 256] = r[u];
        }

        const float4* __restrict__ srcl = (const float4*)g_lse;
        float4* __restrict__ dstl = (float4*)out_lse;
        const size_t n4l = (size_t)lse4;
        const unsigned qb4 = qbase >> 2;
        for (size_t j = (size_t)cid * 256 + tid; j < n4l; j += (size_t)NCOPY * 256) {
            unsigned col = (unsigned)j & 1023u;
            if ((col - qb4) < 32u) continue;
            dstl[j] = srcl[j];
        }
        return;
    }

    // =====================  ATTENTION BRANCH  =====================
    extern __shared__ __half hs[];
    __half* hQ = hs;                 // [128][PH]
    __half* hK = hs + BQ * PH;       // [128][PH]
    __half* hV = hs + 2 * BQ * PH;   // [128][PH]

    const int bh  = blockIdx.x;
    const int b   = bh >> 5;
    const int h   = bh & 31;
    const int kvh = h / (HQ / HKV);
    const int biq  = __ldg(p_biq);
    const int bikv = __ldg(p_bikv);

    const int lane = tid & 31;
    const int w    = tid >> 5;
    const float scale = 0.08838834764831845f;  // 1/sqrt(128)

    // ---------- load + RMS-norm Q,K; load V; convert to half ----------
    {
        const float4 gqv = ((const float4*)(gq + (size_t)h * HD))[lane];
        const float4 gkv = ((const float4*)(gk + (size_t)kvh * HD))[lane];
        for (int r = w * 16; r < w * 16 + 16; ++r) {
            float4 x = ((const float4*)(q + ((size_t)(b * BQ + r) * HQ + h) * HD))[lane];
            float ssq = warp_sum(x.x * x.x + x.y * x.y + x.z * x.z + x.w * x.w);
            float riq = rsqrtf(ssq * (1.0f / HD) + EPSV);
            uint2 uq;
            uq.x = packh2(x.x * riq * gqv.x, x.y * riq * gqv.y);
            uq.y = packh2(x.z * riq * gqv.z, x.w * riq * gqv.w);
            *(uint2*)&hQ[r * PH + lane * 4] = uq;

            float4 y = ((const float4*)(k + ((size_t)(b * BKV + r) * HKV + kvh) * HD))[lane];
            float ssk = warp_sum(y.x * y.x + y.y * y.y + y.z * y.z + y.w * y.w);
            float rik = rsqrtf(ssk * (1.0f / HD) + EPSV);
            uint2 uk;
            uk.x = packh2(y.x * rik * gkv.x, y.y * rik * gkv.y);
            uk.y = packh2(y.z * rik * gkv.z, y.w * rik * gkv.w);
            *(uint2*)&hK[r * PH + lane * 4] = uk;

            float4 z = ((const float4*)(v + ((size_t)(b * BKV + r) * HKV + kvh) * HD))[lane];
            uint2 uv;
            uv.x = packh2(z.x, z.y);
            uv.y = packh2(z.z, z.w);
            *(uint2*)&hV[r * PH + lane * 4] = uv;
        }
    }
    __syncthreads();

    const uint32_t smQ = (uint32_t)__cvta_generic_to_shared(hQ);
    const uint32_t smK = (uint32_t)__cvta_generic_to_shared(hK);
    const uint32_t smV = (uint32_t)__cvta_generic_to_shared(hV);

    // ---------- GEMM1: S strip (16 x 128) = Q strip @ K^T ----------
    uint32_t aQ[8][4];
    {
        const uint32_t abase = smQ +
            (uint32_t)(((w * 16 + (lane & 15)) * PH + ((lane >> 4) << 3)) * 2);
        #pragma unroll
        for (int ks = 0; ks < 8; ++ks)
            ldsm4(aQ[ks][0], aQ[ks][1], aQ[ks][2], aQ[ks][3], abase + ks * 32);
    }

    float sacc[16][4];
    #pragma unroll
    for (int nt = 0; nt < 16; ++nt)
        #pragma unroll
        for (int i = 0; i < 4; ++i) sacc[nt][i] = 0.0f;

    {
        const uint32_t bbase = smK +
            (uint32_t)((((lane & 7)) * PH + (((lane >> 3) & 1) << 3)) * 2);
        #pragma unroll
        for (int nt = 0; nt < 16; ++nt) {
            const uint32_t bb = bbase + (uint32_t)(nt * 8 * PH * 2);
            #pragma unroll
            for (int ks = 0; ks < 8; ++ks) {
                uint32_t b0, b1;
                ldsm2(b0, b1, bb + ks * 32);
                mma16816(sacc[nt], aQ[ks], b0, b1);
            }
        }
    }

    // ---------- softmax on the register strip ----------
    const int g  = lane >> 2;
    const int t  = lane & 3;
    const int qbase = biq * BQ;
    const int kbase = bikv * BKV;
    const int offs  = SKVC - SQC;
    const int qi_lo = qbase + w * 16 + g;
    const int qi_hi = qi_lo + 8;
    const bool qok_lo = (qi_lo < SQC);
    const bool qok_hi = (qi_hi < SQC);

    float m_lo = -INFINITY, m_hi = -INFINITY;
    #pragma unroll
    for (int nt = 0; nt < 16; ++nt) {
        const int c0g = kbase + nt * 8 + t * 2;
        #pragma unroll
        for (int i = 0; i < 4; ++i) {
            const int kj = c0g + (i & 1);
            const int qi = (i < 2) ? qi_lo : qi_hi;
            const bool qok = (i < 2) ? qok_lo : qok_hi;
            float x = sacc[nt][i] * scale;
            float u  = x * (1.0f / CAPV);
            float u2 = u * u;
            float s  = x * (1.0f - u2 * (1.0f / 3.0f) + u2 * u2 * (2.0f / 15.0f));
            const bool allowed = (kj <= qi + offs) && (kj >= qi + offs - WIN) &&
                                 qok && (kj < SKVC);
            s = allowed ? s : -INFINITY;
            sacc[nt][i] = s;
            if (i < 2) m_lo = fmaxf(m_lo, s); else m_hi = fmaxf(m_hi, s);
        }
    }
    #pragma unroll
    for (int o = 1; o <= 2; o <<= 1) {
        m_lo = fmaxf(m_lo, __shfl_xor_sync(0xffffffffu, m_lo, o));
        m_hi = fmaxf(m_hi, __shfl_xor_sync(0xffffffffu, m_hi, o));
    }

    float s_lo = 0.0f, s_hi = 0.0f;
    #pragma unroll
    for (int nt = 0; nt < 16; ++nt) {
        #pragma unroll
        for (int i = 0; i < 4; ++i) {
            const float m = (i < 2) ? m_lo : m_hi;
            float p = (m == -INFINITY) ? 0.0f : __expf(sacc[nt][i] - m);
            sacc[nt][i] = p;
            if (i < 2) s_lo += p; else s_hi += p;
        }
    }
    #pragma unroll
    for (int o = 1; o <= 2; o <<= 1) {
        s_lo += __shfl_xor_sync(0xffffffffu, s_lo, o);
        s_hi += __shfl_xor_sync(0xffffffffu, s_hi, o);
    }

    // ---------- merge coefficients per row (redundant in each quad) ----------
    float co_lo, cbn_lo, co_hi, cbn_hi, lnew_lo, lnew_hi;
    {
        const size_t lbase = ((size_t)b * HQ + h) * SQC;
        #pragma unroll
        for (int half_i = 0; half_i < 2; ++half_i) {
            const float s  = half_i ? s_hi : s_lo;
            const float m  = half_i ? m_hi : m_lo;
            const int   qi = half_i ? qi_hi : qi_lo;
            const float lse_blk = (s > 0.0f && m > -INFINITY) ? (m + logf(s)) : -INFINITY;
            const float lo = __ldg(&g_lse[lbase + qi]);
            const float m2 = fmaxf(lo, lse_blk);
            float lnew, co, cb;
            if (m2 == -INFINITY) {
                lnew = -INFINITY; co = 0.0f; cb = 0.0f;
            } else {
                float e0 = (lo == -INFINITY) ? 0.0f : expf(lo - m2);
                float e1 = (lse_blk == -INFINITY) ? 0.0f : expf(lse_blk - m2);
                lnew = m2 + logf(e0 + e1);
                co = (lo == -INFINITY) ? 0.0f : expf(lo - lnew);
                cb = (lse_blk == -INFINITY) ? 0.0f : expf(lse_blk - lnew);
            }
            const float cbn = (s > 0.0f) ? (cb / s) : 0.0f;
            if (half_i) { co_hi = co; cbn_hi = cbn; lnew_hi = lnew; }
            else        { co_lo = co; cbn_lo = cbn; lnew_lo = lnew; }
        }
        if (t == 0) {
            out_lse[lbase + qi_lo] = lnew_lo;
            out_lse[lbase + qi_hi] = lnew_hi;
        }
    }

    // ---------- re-pack P (C-fragment) into A-fragments for GEMM2 ----------
    uint32_t pa[8][4];
    #pragma unroll
    for (int ks = 0; ks < 8; ++ks) {
        pa[ks][0] = packh2(sacc[2 * ks][0],     sacc[2 * ks][1]);
        pa[ks][1] = packh2(sacc[2 * ks][2],     sacc[2 * ks][3]);
        pa[ks][2] = packh2(sacc[2 * ks + 1][0], sacc[2 * ks + 1][1]);
        pa[ks][3] = packh2(sacc[2 * ks + 1][2], sacc[2 * ks + 1][3]);
    }

    // ---------- GEMM2: O strip (16 x 128) = P @ V ----------
    float oacc[16][4];
    #pragma unroll
    for (int nt = 0; nt < 16; ++nt)
        #pragma unroll
        for (int i = 0; i < 4; ++i) oacc[nt][i] = 0.0f;

    {
        const uint32_t vbase = smV +
            (uint32_t)((((lane & 7) + ((lane >> 3) & 1) * 8) * PH) * 2);
        #pragma unroll
        for (int nt = 0; nt < 16; ++nt) {
            const uint32_t vb = vbase + (uint32_t)(nt * 16);
            #pragma unroll
            for (int ks = 0; ks < 8; ++ks) {
                uint32_t b0, b1;
                ldsm2t(b0, b1, vb + (uint32_t)(ks * 16 * PH * 2));
                mma16816(oacc[nt], pa[ks], b0, b1);
            }
        }
    }

    // ---------- merge with old global O, write ----------
    {
        const size_t base_lo = (((size_t)b * SQC + qi_lo) * HQ + h) * HD;
        const size_t base_hi = (((size_t)b * SQC + qi_hi) * HQ + h) * HD;
        #pragma unroll
        for (int nt = 0; nt < 16; ++nt) {
            const int c = nt * 8 + t * 2;
            float2 g0 = *(const float2*)&g_o[base_lo + c];
            float2 g1 = *(const float2*)&g_o[base_hi + c];
            float2 o0, o1;
            o0.x = co_lo * g0.x + cbn_lo * oacc[nt][0];
            o0.y = co_lo * g0.y + cbn_lo * oacc[nt][1];
            o1.x = co_hi * g1.x + cbn_hi * oacc[nt][2];
            o1.y = co_hi * g1.y + cbn_hi * oacc[nt][3];
            *(float2*)&out_o[base_lo + c] = o0;
            *(float2*)&out_o[base_hi + c] = o1;
        }
    }
}

extern "C" void kernel_launch(void* const* d_in, const int* in_sizes, int n_in,
                              void* d_out, int out_size)
{
    const float* q     = (const float*)d_in[0];
    const float* k     = (const float*)d_in[1];
    const float* v     = (const float*)d_in[2];
    const float* g_o   = (const float*)d_in[3];
    const float* g_lse = (const float*)d_in[4];
    const float* gq    = (const float*)d_in[5];
    const float* gk    = (const float*)d_in[6];
    const int*   biq   = (const int*)d_in[7];
    const int*   bikv  = (const int*)d_in[8];

    float* out = (float*)d_out;

    const int b_dim = in_sizes[0] / (BQ * HQ * HD);                 // 4
    const unsigned long long o_elems   = (unsigned long long)in_sizes[3];
    const unsigned long long lse_elems = (unsigned long long)in_sizes[4];
    const int natt = b_dim * HQ;                                    // 128

    const unsigned long long o4   = o_elems >> 2;
    const unsigned long long lse4 = lse_elems >> 2;

    const size_t smem = (size_t)3 * BQ * PH * sizeof(__half);       // 104448 B
    cudaFuncSetAttribute(oswa_fused,
                         cudaFuncAttributeMaxDynamicSharedMemorySize, (int)smem);

    // attention CTAs first (short now), then 1024 static copy CTAs refill SMs
    oswa_fused<<<natt + NCOPY, 256, smem, 0>>>(
        q, k, v, g_o, g_lse, gq, gk, biq, bikv,
        out, out + o_elems, natt, o4, lse4);
}

// round 9
// speedup vs baseline: 1.8865x; 1.3608x over previous
#include <cuda_runtime.h>
#include <cuda_fp16.h>
#include <math.h>
#include <stdint.h>

// ---- problem constants ----
#define HD   128
#define HQ   32
#define HKV  8
#define SQC  4096
#define SKVC 4096
#define BQ   128
#define BKV  128
#define WIN  512
#define CAPV 50.0f
#define EPSV 1e-5f

#define PH 136   // smem half pitch (272B rows: 16B-aligned, ldmatrix conflict-free)

__device__ __forceinline__ float warp_sum(float v) {
    #pragma unroll
    for (int o = 16; o; o >>= 1) v += __shfl_xor_sync(0xffffffffu, v, o);
    return v;
}

__device__ __forceinline__ void ldsm4(uint32_t& r0, uint32_t& r1, uint32_t& r2, uint32_t& r3,
                                      uint32_t addr) {
    asm volatile("ldmatrix.sync.aligned.m8n8.x4.shared.b16 {%0,%1,%2,%3}, [%4];"
                 : "=r"(r0), "=r"(r1), "=r"(r2), "=r"(r3) : "r"(addr));
}
__device__ __forceinline__ void ldsm2(uint32_t& r0, uint32_t& r1, uint32_t addr) {
    asm volatile("ldmatrix.sync.aligned.m8n8.x2.shared.b16 {%0,%1}, [%2];"
                 : "=r"(r0), "=r"(r1) : "r"(addr));
}
__device__ __forceinline__ void ldsm2t(uint32_t& r0, uint32_t& r1, uint32_t addr) {
    asm volatile("ldmatrix.sync.aligned.m8n8.x2.trans.shared.b16 {%0,%1}, [%2];"
                 : "=r"(r0), "=r"(r1) : "r"(addr));
}
__device__ __forceinline__ void mma16816(float* c, const uint32_t* a, uint32_t b0, uint32_t b1) {
    asm volatile(
        "mma.sync.aligned.m16n8k16.row.col.f32.f16.f16.f32 "
        "{%0,%1,%2,%3}, {%4,%5,%6,%7}, {%8,%9}, {%0,%1,%2,%3};"
        : "+f"(c[0]), "+f"(c[1]), "+f"(c[2]), "+f"(c[3])
        : "r"(a[0]), "r"(a[1]), "r"(a[2]), "r"(a[3]), "r"(b0), "r"(b1));
}
__device__ __forceinline__ uint32_t packh2(float lo, float hi) {
    __half2 h = __floats2half2_rn(lo, hi);
    return *reinterpret_cast<uint32_t*>(&h);
}

// =====================  ATTENTION KERNEL (primary)  =====================
__global__ __launch_bounds__(256, 1)
void oswa_attn(const float* __restrict__ q, const float* __restrict__ k,
               const float* __restrict__ v, const float* __restrict__ g_o,
               const float* __restrict__ g_lse, const float* __restrict__ gq,
               const float* __restrict__ gk, const int* __restrict__ p_biq,
               const int* __restrict__ p_bikv,
               float* __restrict__ out_o, float* __restrict__ out_lse)
{
    // Allow the dependent copy kernel to launch immediately: its write set
    // (non-block rows) is disjoint from ours (block rows), so no sync needed.
    asm volatile("griddepcontrol.launch_dependents;");

    extern __shared__ __half hs[];
    __half* hQ = hs;                 // [128][PH]
    __half* hK = hs + BQ * PH;       // [128][PH]
    __half* hV = hs + 2 * BQ * PH;   // [128][PH]

    const int tid = threadIdx.x;
    const int bh  = blockIdx.x;
    const int b   = bh >> 5;
    const int h   = bh & 31;
    const int kvh = h / (HQ / HKV);
    const int biq  = __ldg(p_biq);
    const int bikv = __ldg(p_bikv);

    const int lane = tid & 31;
    const int w    = tid >> 5;
    const float scale = 0.08838834764831845f;  // 1/sqrt(128)

    // ---------- load + RMS-norm Q,K; load V; convert to half ----------
    {
        const float4 gqv = ((const float4*)(gq + (size_t)h * HD))[lane];
        const float4 gkv = ((const float4*)(gk + (size_t)kvh * HD))[lane];
        for (int r = w * 16; r < w * 16 + 16; ++r) {
            float4 x = ((const float4*)(q + ((size_t)(b * BQ + r) * HQ + h) * HD))[lane];
            float ssq = warp_sum(x.x * x.x + x.y * x.y + x.z * x.z + x.w * x.w);
            float riq = rsqrtf(ssq * (1.0f / HD) + EPSV);
            uint2 uq;
            uq.x = packh2(x.x * riq * gqv.x, x.y * riq * gqv.y);
            uq.y = packh2(x.z * riq * gqv.z, x.w * riq * gqv.w);
            *(uint2*)&hQ[r * PH + lane * 4] = uq;

            float4 y = ((const float4*)(k + ((size_t)(b * BKV + r) * HKV + kvh) * HD))[lane];
            float ssk = warp_sum(y.x * y.x + y.y * y.y + y.z * y.z + y.w * y.w);
            float rik = rsqrtf(ssk * (1.0f / HD) + EPSV);
            uint2 uk;
            uk.x = packh2(y.x * rik * gkv.x, y.y * rik * gkv.y);
            uk.y = packh2(y.z * rik * gkv.z, y.w * rik * gkv.w);
            *(uint2*)&hK[r * PH + lane * 4] = uk;

            float4 z = ((const float4*)(v + ((size_t)(b * BKV + r) * HKV + kvh) * HD))[lane];
            uint2 uv;
            uv.x = packh2(z.x, z.y);
            uv.y = packh2(z.z, z.w);
            *(uint2*)&hV[r * PH + lane * 4] = uv;
        }
    }
    __syncthreads();

    const uint32_t smQ = (uint32_t)__cvta_generic_to_shared(hQ);
    const uint32_t smK = (uint32_t)__cvta_generic_to_shared(hK);
    const uint32_t smV = (uint32_t)__cvta_generic_to_shared(hV);

    // ---------- GEMM1: S strip (16 x 128) = Q strip @ K^T ----------
    uint32_t aQ[8][4];
    {
        const uint32_t abase = smQ +
            (uint32_t)(((w * 16 + (lane & 15)) * PH + ((lane >> 4) << 3)) * 2);
        #pragma unroll
        for (int ks = 0; ks < 8; ++ks)
            ldsm4(aQ[ks][0], aQ[ks][1], aQ[ks][2], aQ[ks][3], abase + ks * 32);
    }

    float sacc[16][4];
    #pragma unroll
    for (int nt = 0; nt < 16; ++nt)
        #pragma unroll
        for (int i = 0; i < 4; ++i) sacc[nt][i] = 0.0f;

    {
        const uint32_t bbase = smK +
            (uint32_t)((((lane & 7)) * PH + (((lane >> 3) & 1) << 3)) * 2);
        #pragma unroll
        for (int nt = 0; nt < 16; ++nt) {
            const uint32_t bb = bbase + (uint32_t)(nt * 8 * PH * 2);
            #pragma unroll
            for (int ks = 0; ks < 8; ++ks) {
                uint32_t b0, b1;
                ldsm2(b0, b1, bb + ks * 32);
                mma16816(sacc[nt], aQ[ks], b0, b1);
            }
        }
    }

    // ---------- softmax on the register strip ----------
    const int g  = lane >> 2;
    const int t  = lane & 3;
    const int qbase = biq * BQ;
    const int kbase = bikv * BKV;
    const int offs  = SKVC - SQC;
    const int qi_lo = qbase + w * 16 + g;
    const int qi_hi = qi_lo + 8;
    const bool qok_lo = (qi_lo < SQC);
    const bool qok_hi = (qi_hi < SQC);

    float m_lo = -INFINITY, m_hi = -INFINITY;
    #pragma unroll
    for (int nt = 0; nt < 16; ++nt) {
        const int c0g = kbase + nt * 8 + t * 2;
        #pragma unroll
        for (int i = 0; i < 4; ++i) {
            const int kj = c0g + (i & 1);
            const int qi = (i < 2) ? qi_lo : qi_hi;
            const bool qok = (i < 2) ? qok_lo : qok_hi;
            float x = sacc[nt][i] * scale;
            float u  = x * (1.0f / CAPV);
            float u2 = u * u;
            float s  = x * (1.0f - u2 * (1.0f / 3.0f) + u2 * u2 * (2.0f / 15.0f));
            const bool allowed = (kj <= qi + offs) && (kj >= qi + offs - WIN) &&
                                 qok && (kj < SKVC);
            s = allowed ? s : -INFINITY;
            sacc[nt][i] = s;
            if (i < 2) m_lo = fmaxf(m_lo, s); else m_hi = fmaxf(m_hi, s);
        }
    }
    #pragma unroll
    for (int o = 1; o <= 2; o <<= 1) {
        m_lo = fmaxf(m_lo, __shfl_xor_sync(0xffffffffu, m_lo, o));
        m_hi = fmaxf(m_hi, __shfl_xor_sync(0xffffffffu, m_hi, o));
    }

    float s_lo = 0.0f, s_hi = 0.0f;
    #pragma unroll
    for (int nt = 0; nt < 16; ++nt) {
        #pragma unroll
        for (int i = 0; i < 4; ++i) {
            const float m = (i < 2) ? m_lo : m_hi;
            float p = (m == -INFINITY) ? 0.0f : __expf(sacc[nt][i] - m);
            sacc[nt][i] = p;
            if (i < 2) s_lo += p; else s_hi += p;
        }
    }
    #pragma unroll
    for (int o = 1; o <= 2; o <<= 1) {
        s_lo += __shfl_xor_sync(0xffffffffu, s_lo, o);
        s_hi += __shfl_xor_sync(0xffffffffu, s_hi, o);
    }

    // ---------- merge coefficients per row (redundant in each quad) ----------
    float co_lo, cbn_lo, co_hi, cbn_hi, lnew_lo, lnew_hi;
    {
        const size_t lbase = ((size_t)b * HQ + h) * SQC;
        #pragma unroll
        for (int half_i = 0; half_i < 2; ++half_i) {
            const float s  = half_i ? s_hi : s_lo;
            const float m  = half_i ? m_hi : m_lo;
            const int   qi = half_i ? qi_hi : qi_lo;
            const float lse_blk = (s > 0.0f && m > -INFINITY) ? (m + logf(s)) : -INFINITY;
            const float lo = __ldg(&g_lse[lbase + qi]);
            const float m2 = fmaxf(lo, lse_blk);
            float lnew, co, cb;
            if (m2 == -INFINITY) {
                lnew = -INFINITY; co = 0.0f; cb = 0.0f;
            } else {
                float e0 = (lo == -INFINITY) ? 0.0f : expf(lo - m2);
                float e1 = (lse_blk == -INFINITY) ? 0.0f : expf(lse_blk - m2);
                lnew = m2 + logf(e0 + e1);
                co = (lo == -INFINITY) ? 0.0f : expf(lo - lnew);
                cb = (lse_blk == -INFINITY) ? 0.0f : expf(lse_blk - lnew);
            }
            const float cbn = (s > 0.0f) ? (cb / s) : 0.0f;
            if (half_i) { co_hi = co; cbn_hi = cbn; lnew_hi = lnew; }
            else        { co_lo = co; cbn_lo = cbn; lnew_lo = lnew; }
        }
        if (t == 0) {
            out_lse[lbase + qi_lo] = lnew_lo;
            out_lse[lbase + qi_hi] = lnew_hi;
        }
    }

    // ---------- re-pack P (C-fragment) into A-fragments for GEMM2 ----------
    uint32_t pa[8][4];
    #pragma unroll
    for (int ks = 0; ks < 8; ++ks) {
        pa[ks][0] = packh2(sacc[2 * ks][0],     sacc[2 * ks][1]);
        pa[ks][1] = packh2(sacc[2 * ks][2],     sacc[2 * ks][3]);
        pa[ks][2] = packh2(sacc[2 * ks + 1][0], sacc[2 * ks + 1][1]);
        pa[ks][3] = packh2(sacc[2 * ks + 1][2], sacc[2 * ks + 1][3]);
    }

    // ---------- GEMM2: O strip (16 x 128) = P @ V ----------
    float oacc[16][4];
    #pragma unroll
    for (int nt = 0; nt < 16; ++nt)
        #pragma unroll
        for (int i = 0; i < 4; ++i) oacc[nt][i] = 0.0f;

    {
        const uint32_t vbase = smV +
            (uint32_t)((((lane & 7) + ((lane >> 3) & 1) * 8) * PH) * 2);
        #pragma unroll
        for (int nt = 0; nt < 16; ++nt) {
            const uint32_t vb = vbase + (uint32_t)(nt * 16);
            #pragma unroll
            for (int ks = 0; ks < 8; ++ks) {
                uint32_t b0, b1;
                ldsm2t(b0, b1, vb + (uint32_t)(ks * 16 * PH * 2));
                mma16816(oacc[nt], pa[ks], b0, b1);
            }
        }
    }

    // ---------- merge with old global O, write ----------
    {
        const size_t base_lo = (((size_t)b * SQC + qi_lo) * HQ + h) * HD;
        const size_t base_hi = (((size_t)b * SQC + qi_hi) * HQ + h) * HD;
        #pragma unroll
        for (int nt = 0; nt < 16; ++nt) {
            const int c = nt * 8 + t * 2;
            float2 g0 = *(const float2*)&g_o[base_lo + c];
            float2 g1 = *(const float2*)&g_o[base_hi + c];
            float2 o0, o1;
            o0.x = co_lo * g0.x + cbn_lo * oacc[nt][0];
            o0.y = co_lo * g0.y + cbn_lo * oacc[nt][1];
            o1.x = co_hi * g1.x + cbn_hi * oacc[nt][2];
            o1.y = co_hi * g1.y + cbn_hi * oacc[nt][3];
            *(float2*)&out_o[base_lo + c] = o0;
            *(float2*)&out_o[base_hi + c] = o1;
        }
    }
}

// =====================  COPY KERNEL (PDL secondary)  =====================
// Low-register, high-occupancy bulk copy. Writes only NON-block rows, so it
// is independent of the attention kernel and may run fully concurrently.
__global__ __launch_bounds__(256)
void oswa_copy(const float4* __restrict__ so, float4* __restrict__ doo,
               const float4* __restrict__ sl, float4* __restrict__ dl,
               const int* __restrict__ p_biq,
               unsigned long long o4, unsigned long long lse4)
{
    const unsigned qbase = (unsigned)(__ldg(p_biq) * BQ);
    const int tid = threadIdx.x;

    // ---- global_o ----
    const size_t stride = (size_t)gridDim.x * 2048;   // 256 thr * 8 f4
    for (size_t i = (size_t)blockIdx.x * 2048 + tid; i < (size_t)o4; i += stride) {
        float4 r[8]; bool ok[8];
        #pragma unroll
        for (int u = 0; u < 8; ++u) {
            const size_t ii = i + (size_t)u * 256;
            ok[u] = (ii < (size_t)o4);
            if (ok[u]) {
                const unsigned row = (unsigned)(ii >> 10) & (SQC - 1u); // 1024 f4/row
                if ((row - qbase) < (unsigned)BQ) ok[u] = false;        // attention owns
                else r[u] = __ldcs(so + ii);
            }
        }
        #pragma unroll
        for (int u = 0; u < 8; ++u)
            if (ok[u]) __stcs(doo + i + (size_t)u * 256, r[u]);
    }

    // ---- global_lse ----
    const unsigned qb4 = qbase >> 2;
    for (size_t j = (size_t)blockIdx.x * 256 + tid; j < (size_t)lse4;
         j += (size_t)gridDim.x * 256) {
        const unsigned col = (unsigned)j & 1023u;     // 1024 f4 per (b,h) row
        if ((col - qb4) < 32u) continue;
        __stcs(dl + j, __ldcs(sl + j));
    }
}

extern "C" void kernel_launch(void* const* d_in, const int* in_sizes, int n_in,
                              void* d_out, int out_size)
{
    const float* q     = (const float*)d_in[0];
    const float* k     = (const float*)d_in[1];
    const float* v     = (const float*)d_in[2];
    const float* g_o   = (const float*)d_in[3];
    const float* g_lse = (const float*)d_in[4];
    const float* gq    = (const float*)d_in[5];
    const float* gk    = (const float*)d_in[6];
    const int*   biq   = (const int*)d_in[7];
    const int*   bikv  = (const int*)d_in[8];

    float* out = (float*)d_out;

    const int b_dim = in_sizes[0] / (BQ * HQ * HD);                 // 4
    const unsigned long long o_elems   = (unsigned long long)in_sizes[3];
    const unsigned long long lse_elems = (unsigned long long)in_sizes[4];
    const int natt = b_dim * HQ;                                    // 128

    const unsigned long long o4   = o_elems >> 2;
    const unsigned long long lse4 = lse_elems >> 2;

    const size_t smem = (size_t)3 * BQ * PH * sizeof(__half);       // 104448 B
    cudaFuncSetAttribute(oswa_attn,
                         cudaFuncAttributeMaxDynamicSharedMemorySize, (int)smem);

    // Primary: attention (fires launch_dependents at entry).
    oswa_attn<<<natt, 256, smem, 0>>>(
        q, k, v, g_o, g_lse, gq, gk, biq, bikv, out, out + o_elems);

    // Secondary: bulk copy with Programmatic Dependent Launch -> overlaps
    // with attention (disjoint write sets; no griddepcontrol.wait needed).
    cudaLaunchConfig_t cfg = {};
    cfg.gridDim  = dim3(4096, 1, 1);
    cfg.blockDim = dim3(256, 1, 1);
    cfg.dynamicSmemBytes = 0;
    cfg.stream = 0;
    cudaLaunchAttribute attrs[1];
    attrs[0].id = cudaLaunchAttributeProgrammaticStreamSerialization;
    attrs[0].val.programmaticStreamSerializationAllowed = 1;
    cfg.attrs = attrs;
    cfg.numAttrs = 1;
    cudaLaunchKernelEx(&cfg, oswa_copy,
                       (const float4*)g_o, (float4*)out,
                       (const float4*)g_lse, (float4*)(out + o_elems),
                       biq, o4, lse4);
}